// round 14
// baseline (speedup 1.0000x reference)
#include <cuda_runtime.h>
#include <cuda_bf16.h>
#include <math.h>
#include <stdint.h>

// Problem constants
#define BB 2
#define SS 2048
#define EE 1024
#define HH 16
#define DD 64
#define MROWS (BB * SS)   // 4096
#define NW (EE * EE)      // 1048576

// Scratch (__device__ globals; allocation-free rule)
__device__ __nv_bfloat16 g_ahi[MROWS * EE];
__device__ __nv_bfloat16 g_alo[MROWS * EE];
__device__ __nv_bfloat16 g_whi[4 * NW];
__device__ __nv_bfloat16 g_wlo[4 * NW];
__device__ __nv_bfloat16 g_qhi[MROWS * EE];
__device__ __nv_bfloat16 g_qlo[MROWS * EE];
__device__ __nv_bfloat16 g_khi[MROWS * EE];
__device__ __nv_bfloat16 g_klo[MROWS * EE];
__device__ __nv_bfloat16 g_vhi[MROWS * EE];
__device__ __nv_bfloat16 g_vlo[MROWS * EE];
__device__ float2 g_rope[SS * 32];

// ---------------------------------------------------------------------------
// Helpers
// ---------------------------------------------------------------------------
static __device__ __forceinline__ uint32_t smem_u32(const void* p) {
    uint32_t a;
    asm("{ .reg .u64 t; cvta.to.shared.u64 t, %1; cvt.u32.u64 %0, t; }"
        : "=r"(a) : "l"(p));
    return a;
}

#define SWZ(o)   ((o) ^ (((o) >> 3) & 0x70))
#define SWZ64(o) ((o) ^ (((o) >> 3) & 0x30))

static __device__ __forceinline__ void cp16(uint32_t saddr, const void* g) {
    asm volatile("cp.async.cg.shared.global [%0], [%1], 16;"
                 :: "r"(saddr), "l"(g));
}
#define CP_COMMIT() asm volatile("cp.async.commit_group;")
#define CP_WAIT(n)  asm volatile("cp.async.wait_group %0;" :: "n"(n))

static __device__ __forceinline__ void ldsm4(uint32_t* r, uint32_t addr) {
    asm volatile("ldmatrix.sync.aligned.m8n8.x4.shared.b16 {%0,%1,%2,%3}, [%4];"
                 : "=r"(r[0]), "=r"(r[1]), "=r"(r[2]), "=r"(r[3]) : "r"(addr));
}

static __device__ __forceinline__ void ldsm4t(uint32_t* r, uint32_t addr) {
    asm volatile("ldmatrix.sync.aligned.m8n8.x4.trans.shared.b16 {%0,%1,%2,%3}, [%4];"
                 : "=r"(r[0]), "=r"(r[1]), "=r"(r[2]), "=r"(r[3]) : "r"(addr));
}

static __device__ __forceinline__ void mma_bf16(float* c, const uint32_t* a,
                                                const uint32_t* b) {
    asm volatile(
        "mma.sync.aligned.m16n8k16.row.col.f32.bf16.bf16.f32 "
        "{%0,%1,%2,%3}, {%4,%5,%6,%7}, {%8,%9}, {%0,%1,%2,%3};"
        : "+f"(c[0]), "+f"(c[1]), "+f"(c[2]), "+f"(c[3])
        : "r"(a[0]), "r"(a[1]), "r"(a[2]), "r"(a[3]), "r"(b[0]), "r"(b[1]));
}

// One-instruction pack of two floats into bf16x2 (lo -> low half)
static __device__ __forceinline__ uint32_t cvt2_bf16(float lo, float hi) {
    uint32_t r;
    asm("cvt.rn.bf16x2.f32 %0, %1, %2;" : "=r"(r) : "f"(hi), "f"(lo));
    return r;
}
static __device__ __forceinline__ float bf_lo_f(uint32_t p) {
    return __int_as_float(p << 16);
}
static __device__ __forceinline__ float bf_hi_f(uint32_t p) {
    return __int_as_float(p & 0xFFFF0000u);
}

// FFMA-only 2^x (input already in log2 domain)
static __device__ __forceinline__ float fast_exp2(float x) {
    x = fmaxf(x, -126.0f);
    float fn = x + 12582912.0f;
    int n = __float_as_int(fn) - 0x4B400000;
    float f = x - (fn - 12582912.0f);
    float r = 0.0013333558f;
    r = fmaf(r, f, 0.0096181291f);
    r = fmaf(r, f, 0.0555041087f);
    r = fmaf(r, f, 0.2402265069f);
    r = fmaf(r, f, 0.6931471806f);
    r = fmaf(r, f, 1.0f);
    return __int_as_float(__float_as_int(r) + (n << 23));
}

// score pre-scale folded into Q: log2(e)/32
#define QSCALE 0.045084441f

// ---------------------------------------------------------------------------
// rope cos/sin table
// ---------------------------------------------------------------------------
__global__ void rope_table_kernel() {
    int idx = blockIdx.x * blockDim.x + threadIdx.x;
    if (idx >= SS * 32) return;
    int s = idx >> 5, i = idx & 31;
    float theta = expf(-logf(10000.0f) * (2.0f * (float)i) / 64.0f);
    float c, sn;
    sincosf((float)s * theta, &sn, &c);
    g_rope[idx] = make_float2(c, sn);
}

// ---------------------------------------------------------------------------
// fp32 -> bf16 hi/lo split, float4 vectorized
// ---------------------------------------------------------------------------
static __device__ __forceinline__ void split4_store(
    float4 v, __nv_bfloat16* hi, __nv_bfloat16* lo, size_t i4) {
    uint32_t h01 = cvt2_bf16(v.x, v.y);
    uint32_t h23 = cvt2_bf16(v.z, v.w);
    uint32_t l01 = cvt2_bf16(v.x - bf_lo_f(h01), v.y - bf_hi_f(h01));
    uint32_t l23 = cvt2_bf16(v.z - bf_lo_f(h23), v.w - bf_hi_f(h23));
    reinterpret_cast<uint2*>(hi)[i4] = make_uint2(h01, h23);
    reinterpret_cast<uint2*>(lo)[i4] = make_uint2(l01, l23);
}

__global__ void split_x_kernel(const float* __restrict__ src,
                               __nv_bfloat16* __restrict__ hi,
                               __nv_bfloat16* __restrict__ lo, int n4) {
    int i = blockIdx.x * blockDim.x + threadIdx.x;
    if (i >= n4) return;
    split4_store(reinterpret_cast<const float4*>(src)[i], hi, lo, i);
}

__global__ void split_w_kernel(const float* __restrict__ w0,
                               const float* __restrict__ w1,
                               const float* __restrict__ w2,
                               const float* __restrict__ w3,
                               __nv_bfloat16* __restrict__ hi,
                               __nv_bfloat16* __restrict__ lo) {
    int i = blockIdx.x * blockDim.x + threadIdx.x;   // 0 .. 4*NW/4-1
    int z = i >> 18;
    int loc = i & 0x3FFFF;
    const float* w = (z == 0) ? w0 : (z == 1) ? w1 : (z == 2) ? w2 : w3;
    split4_store(reinterpret_cast<const float4*>(w)[loc], hi, lo, i);
}

// ---------------------------------------------------------------------------
// Persistent warp-MMA GEMM (QKV): CTA 128x64, 4 warps (warp 64x32), BK=32,
// 3-stage cp.async, SW64. 444 persistent CTAs loop over 1536 logical tiles
// (task -> x=col, y=row, z=weight/epilogue) to eliminate wave quantization.
// ---------------------------------------------------------------------------
#define BM 128
#define BN 64
#define BK 32
#define KTILES (EE / BK)                 // 32
#define A_T (BM * BK * 2)                // 8192
#define B_T (BN * BK * 2)                // 4096
#define STAGE_B (2 * A_T + 2 * B_T)      // 24576
#define GEMM_SMEM (3 * STAGE_B)          // 73728
#define QKV_TASKS 1536
#define QKV_GRID 444                     // 3 CTAs/SM * 148 SMs

__global__ void __launch_bounds__(128, 3) gemm_mma(
    const __nv_bfloat16* __restrict__ Ahi, const __nv_bfloat16* __restrict__ Alo,
    const __nv_bfloat16* __restrict__ Whi, const __nv_bfloat16* __restrict__ Wlo,
    __nv_bfloat16* __restrict__ qhi, __nv_bfloat16* __restrict__ qlo,
    __nv_bfloat16* __restrict__ khi, __nv_bfloat16* __restrict__ klo,
    __nv_bfloat16* __restrict__ vhi, __nv_bfloat16* __restrict__ vlo) {
    extern __shared__ __align__(1024) char smem[];
    const uint32_t sb = smem_u32(smem);

    const int tid = threadIdx.x;
    const int wid = tid >> 5;
    const int lid = tid & 31;
    const int wm = wid & 1;
    const int wn = wid >> 1;              // 0..1
    const int q = lid >> 3, rin = lid & 7;

    const int O_AHI = 0, O_ALO = A_T, O_BHI = 2 * A_T, O_BLO = 2 * A_T + B_T;

    for (int task = blockIdx.x; task < QKV_TASKS; task += gridDim.x) {
        const int row0 = ((task >> 4) & 31) * BM;
        const int col0 = (task & 15) * BN;
        const int z = task >> 9;

        const __nv_bfloat16* Bhi = Whi + (size_t)z * NW;
        const __nv_bfloat16* Blo = Wlo + (size_t)z * NW;

        __syncthreads();   // protect smem ring from previous task

        float acc[4][4][4] = {};

        auto load_tiles = [&](int st, int kt) {
            const uint32_t stb = sb + st * STAGE_B;
            const int k0 = kt * BK;
#pragma unroll
            for (int i = 0; i < 4; i++) {
                int c = tid + i * 128;        // 0..511
                int r = c >> 2;               // 0..127
                int cb = (c & 3) * 16;
                uint32_t so = SWZ64((uint32_t)(r * 64 + cb));
                size_t ga = (size_t)(row0 + r) * EE + k0 + (c & 3) * 8;
                cp16(stb + O_AHI + so, Ahi + ga);
                cp16(stb + O_ALO + so, Alo + ga);
            }
#pragma unroll
            for (int i = 0; i < 2; i++) {
                int c = tid + i * 128;        // 0..255
                int r = c >> 2;               // 0..63
                int cb = (c & 3) * 16;
                uint32_t so = SWZ64((uint32_t)(r * 64 + cb));
                size_t gb = (size_t)(col0 + r) * EE + k0 + (c & 3) * 8;
                cp16(stb + O_BHI + so, Bhi + gb);
                cp16(stb + O_BLO + so, Blo + gb);
            }
        };

        load_tiles(0, 0);
        CP_COMMIT();
        load_tiles(1, 1);
        CP_COMMIT();

        for (int kt = 0; kt < KTILES; kt++) {
            if (kt < KTILES - 1) { CP_WAIT(1); } else { CP_WAIT(0); }
            __syncthreads();
            if (kt + 2 < KTILES) {
                int st = kt + 2;
                st = st - (st / 3) * 3;
                load_tiles(st, kt + 2);
                CP_COMMIT();
            }

            const int cur = kt - (kt / 3) * 3;
            const uint32_t stb = sb + cur * STAGE_B;

#pragma unroll
            for (int ks = 0; ks < 2; ks++) {
                const int kb = ks * 32;
                uint32_t ahi[4][4], alo[4][4], bhi[2][4], blo[2][4];
#pragma unroll
                for (int mt = 0; mt < 4; mt++) {
                    uint32_t off = SWZ64((uint32_t)(
                        (wm * 64 + mt * 16 + (q & 1) * 8 + rin) * 64 + kb + (q >> 1) * 16));
                    ldsm4(ahi[mt], stb + O_AHI + off);
                    ldsm4(alo[mt], stb + O_ALO + off);
                }
#pragma unroll
                for (int p = 0; p < 2; p++) {
                    uint32_t off = SWZ64((uint32_t)(
                        (wn * 32 + p * 16 + (q >> 1) * 8 + rin) * 64 + kb + (q & 1) * 16));
                    ldsm4(bhi[p], stb + O_BHI + off);
                    ldsm4(blo[p], stb + O_BLO + off);
                }
#pragma unroll
                for (int mt = 0; mt < 4; mt++)
#pragma unroll
                    for (int nt = 0; nt < 4; nt++) {
                        const uint32_t* bh = &bhi[nt >> 1][(nt & 1) * 2];
                        const uint32_t* bl = &blo[nt >> 1][(nt & 1) * 2];
                        mma_bf16(acc[mt][nt], ahi[mt], bh);
                        mma_bf16(acc[mt][nt], ahi[mt], bl);
                        mma_bf16(acc[mt][nt], alo[mt], bh);
                    }
            }
        }

        const int r_base = row0 + wm * 64 + (lid >> 2);
        const int c_base = col0 + wn * 32 + (lid & 3) * 2;

        __nv_bfloat16* Dhi = (z == 0) ? qhi : (z == 1) ? khi : vhi;
        __nv_bfloat16* Dlo = (z == 0) ? qlo : (z == 1) ? klo : vlo;
        const int mode = (z == 2) ? 2 : 1;
        const float qs = (z == 0) ? QSCALE : 1.0f;
#pragma unroll
        for (int mt = 0; mt < 4; mt++)
#pragma unroll
            for (int nt = 0; nt < 4; nt++) {
                int gr = r_base + mt * 16;
                int gc = c_base + nt * 8;
                int hh = gc >> 6, d = gc & 63, ii = d >> 1;
                int b_ = gr >> 11;
                int s1 = gr & (SS - 1);
                int s2 = (gr + 8) & (SS - 1);
                float v0 = acc[mt][nt][0], v1 = acc[mt][nt][1];
                float v2 = acc[mt][nt][2], v3 = acc[mt][nt][3];
                if (mode == 1) {
                    float2 cs1 = g_rope[(s1 << 5) + ii];
                    float2 cs2 = g_rope[(s2 << 5) + ii];
                    float t0 = v0 * cs1.x - v1 * cs1.y;
                    v1 = (v0 * cs1.y + v1 * cs1.x) * qs; v0 = t0 * qs;
                    t0 = v2 * cs2.x - v3 * cs2.y;
                    v3 = (v2 * cs2.y + v3 * cs2.x) * qs; v2 = t0 * qs;
                }
                size_t o1 = ((size_t)((b_ * HH + hh) * SS + s1)) * 64 + d;
                size_t o2 = ((size_t)((b_ * HH + hh) * SS + s2)) * 64 + d;
                uint32_t h01 = cvt2_bf16(v0, v1);
                uint32_t h23 = cvt2_bf16(v2, v3);
                *reinterpret_cast<uint32_t*>(Dhi + o1) = h01;
                *reinterpret_cast<uint32_t*>(Dhi + o2) = h23;
                *reinterpret_cast<uint32_t*>(Dlo + o1) =
                    cvt2_bf16(v0 - bf_lo_f(h01), v1 - bf_hi_f(h01));
                *reinterpret_cast<uint32_t*>(Dlo + o2) =
                    cvt2_bf16(v2 - bf_lo_f(h23), v3 - bf_hi_f(h23));
            }
    }
}

// ---------------------------------------------------------------------------
// Persistent Wo GEMM: CTA 64x64, 4 warps (warp 32x32), BK=32, 3-stage.
// 592 persistent CTAs over 1024 tiles. fp32 output.
// ---------------------------------------------------------------------------
#define BM2 64
#define BN2 64
#define A2_T (BM2 * BK * 2)              // 4096
#define B2_T (BN2 * BK * 2)              // 4096
#define STAGE2 (2 * A2_T + 2 * B2_T)     // 16384
#define GEMM64_SMEM (3 * STAGE2)         // 49152
#define WO_TASKS 1024
#define WO_GRID 592                      // 4 CTAs/SM * 148 SMs

__global__ void __launch_bounds__(128, 4) gemm_mma64(
    const __nv_bfloat16* __restrict__ Ahi, const __nv_bfloat16* __restrict__ Alo,
    const __nv_bfloat16* __restrict__ Bhi, const __nv_bfloat16* __restrict__ Blo,
    float* __restrict__ C) {
    extern __shared__ __align__(1024) char smem[];
    const uint32_t sb = smem_u32(smem);

    const int tid = threadIdx.x;
    const int wid = tid >> 5;
    const int lid = tid & 31;
    const int wm = wid & 1;
    const int wn = wid >> 1;              // 0..1
    const int q = lid >> 3, rin = lid & 7;

    const int O_AHI = 0, O_ALO = A2_T, O_BHI = 2 * A2_T, O_BLO = 2 * A2_T + B2_T;

    for (int task = blockIdx.x; task < WO_TASKS; task += gridDim.x) {
        const int row0 = (task >> 4) * BM2;
        const int col0 = (task & 15) * BN2;

        __syncthreads();

        float acc[2][4][4] = {};

        auto load_tiles = [&](int st, int kt) {
            const uint32_t stb = sb + st * STAGE2;
            const int k0 = kt * BK;
#pragma unroll
            for (int i = 0; i < 2; i++) {
                int c = tid + i * 128;        // 0..255
                int r = c >> 2;               // 0..63
                int cb = (c & 3) * 16;
                uint32_t so = SWZ64((uint32_t)(r * 64 + cb));
                size_t ga = (size_t)(row0 + r) * EE + k0 + (c & 3) * 8;
                cp16(stb + O_AHI + so, Ahi + ga);
                cp16(stb + O_ALO + so, Alo + ga);
                size_t gb = (size_t)(col0 + r) * EE + k0 + (c & 3) * 8;
                cp16(stb + O_BHI + so, Bhi + gb);
                cp16(stb + O_BLO + so, Blo + gb);
            }
        };

        load_tiles(0, 0);
        CP_COMMIT();
        load_tiles(1, 1);
        CP_COMMIT();

        for (int kt = 0; kt < KTILES; kt++) {
            if (kt < KTILES - 1) { CP_WAIT(1); } else { CP_WAIT(0); }
            __syncthreads();
            if (kt + 2 < KTILES) {
                int st = kt + 2;
                st = st - (st / 3) * 3;
                load_tiles(st, kt + 2);
                CP_COMMIT();
            }

            const int cur = kt - (kt / 3) * 3;
            const uint32_t stb = sb + cur * STAGE2;

#pragma unroll
            for (int ks = 0; ks < 2; ks++) {
                const int kb = ks * 32;
                uint32_t ahi[2][4], alo[2][4], bhi[2][4], blo[2][4];
#pragma unroll
                for (int mt = 0; mt < 2; mt++) {
                    uint32_t off = SWZ64((uint32_t)(
                        (wm * 32 + mt * 16 + (q & 1) * 8 + rin) * 64 + kb + (q >> 1) * 16));
                    ldsm4(ahi[mt], stb + O_AHI + off);
                    ldsm4(alo[mt], stb + O_ALO + off);
                }
#pragma unroll
                for (int p = 0; p < 2; p++) {
                    uint32_t off = SWZ64((uint32_t)(
                        (wn * 32 + p * 16 + (q >> 1) * 8 + rin) * 64 + kb + (q & 1) * 16));
                    ldsm4(bhi[p], stb + O_BHI + off);
                    ldsm4(blo[p], stb + O_BLO + off);
                }
#pragma unroll
                for (int mt = 0; mt < 2; mt++)
#pragma unroll
                    for (int nt = 0; nt < 4; nt++) {
                        const uint32_t* bh = &bhi[nt >> 1][(nt & 1) * 2];
                        const uint32_t* bl = &blo[nt >> 1][(nt & 1) * 2];
                        mma_bf16(acc[mt][nt], ahi[mt], bh);
                        mma_bf16(acc[mt][nt], ahi[mt], bl);
                        mma_bf16(acc[mt][nt], alo[mt], bh);
                    }
            }
        }

        const int r_base = row0 + wm * 32 + (lid >> 2);
        const int c_base = col0 + wn * 32 + (lid & 3) * 2;
#pragma unroll
        for (int mt = 0; mt < 2; mt++)
#pragma unroll
            for (int nt = 0; nt < 4; nt++) {
                int r = r_base + mt * 16;
                int c = c_base + nt * 8;
                *reinterpret_cast<float2*>(C + (size_t)r * EE + c) =
                    make_float2(acc[mt][nt][0], acc[mt][nt][1]);
                *reinterpret_cast<float2*>(C + (size_t)(r + 8) * EE + c) =
                    make_float2(acc[mt][nt][2], acc[mt][nt][3]);
            }
    }
}

// ---------------------------------------------------------------------------
// Warp-MMA causal flash attention (unchanged from round 13).
// ---------------------------------------------------------------------------
#define FQ 128
#define FK 64
#define KV_STAGE 32768
#define FLASH_SMEM (2 * KV_STAGE)   // 65536

__global__ void __launch_bounds__(128, 2) flash_mma(
    const __nv_bfloat16* __restrict__ qhi, const __nv_bfloat16* __restrict__ qlo,
    const __nv_bfloat16* __restrict__ khi, const __nv_bfloat16* __restrict__ klo,
    const __nv_bfloat16* __restrict__ vhi, const __nv_bfloat16* __restrict__ vlo,
    __nv_bfloat16* __restrict__ ohi, __nv_bfloat16* __restrict__ olo) {
    extern __shared__ __align__(1024) char smem[];
    const uint32_t sb = smem_u32(smem);
    const int tid = threadIdx.x;
    const int wid = tid >> 5;
    const int lid = tid & 31;
    const int bh = blockIdx.y;
    const int qt = gridDim.x - 1 - blockIdx.x;
    const int q0 = qt * FQ;
    const int b = bh >> 4, h = bh & 15;
    const int qq = lid >> 3, rin = lid & 7;

    // ---- stage Q through stage-0 smem, capture fragments in registers ----
#pragma unroll
    for (int i = 0; i < 8; i++) {
        int c = i * 128 + tid;
        int r = c >> 3, cb = c & 7;
        uint32_t so = SWZ((uint32_t)(r * 128 + cb * 16));
        size_t g = ((size_t)bh * SS + q0 + r) * 64 + cb * 8;
        cp16(sb + so, qhi + g);
        cp16(sb + 16384 + so, qlo + g);
    }
    CP_COMMIT();
    CP_WAIT(0);
    __syncthreads();

    uint32_t qfh[2][4][4], qfl[2][4][4];
#pragma unroll
    for (int mt = 0; mt < 2; mt++)
#pragma unroll
        for (int kd = 0; kd < 4; kd++) {
            uint32_t off = SWZ((uint32_t)(
                (wid * 32 + mt * 16 + (qq & 1) * 8 + rin) * 128 +
                kd * 32 + (qq >> 1) * 16));
            ldsm4(qfh[mt][kd], sb + off);
            ldsm4(qfl[mt][kd], sb + 16384 + off);
        }
    __syncthreads();

    auto load_kv = [&](int st, int kt) {
        const uint32_t stb = sb + st * KV_STAGE;
        const size_t rb = (size_t)bh * SS + (size_t)kt * FK;
#pragma unroll
        for (int i = 0; i < 4; i++) {
            int c = i * 128 + tid;
            int r = c >> 3, cb = c & 7;
            uint32_t so = SWZ((uint32_t)(r * 128 + cb * 16));
            size_t g = (rb + r) * 64 + cb * 8;
            cp16(stb + so,         khi + g);
            cp16(stb + 8192 + so,  klo + g);
            cp16(stb + 16384 + so, vhi + g);
            cp16(stb + 24576 + so, vlo + g);
        }
    };

    float o[2][8][4] = {};
    float mrow[4] = {-1e30f, -1e30f, -1e30f, -1e30f};
    float lrow[4] = {};   // per-lane partials; cross-lane reduce at end

    const int nkt = 2 * qt + 2;
    load_kv(0, 0);
    CP_COMMIT();

    for (int kt = 0; kt < nkt; kt++) {
        if (kt + 1 < nkt) {
            load_kv((kt + 1) & 1, kt + 1);
            CP_COMMIT();
            CP_WAIT(1);
        } else {
            CP_WAIT(0);
        }
        __syncthreads();

        const uint32_t stb = sb + (kt & 1) * KV_STAGE;
        const int k0 = kt * FK;

        float s[2][8][4] = {};
#pragma unroll
        for (int kd = 0; kd < 4; kd++) {
            uint32_t kh[4][4], kl[4][4];
#pragma unroll
            for (int p = 0; p < 4; p++) {
                uint32_t off = SWZ((uint32_t)(
                    (p * 16 + (qq >> 1) * 8 + rin) * 128 + kd * 32 + (qq & 1) * 16));
                ldsm4(kh[p], stb + off);
                ldsm4(kl[p], stb + 8192 + off);
            }
#pragma unroll
            for (int mt = 0; mt < 2; mt++)
#pragma unroll
                for (int nt = 0; nt < 8; nt++) {
                    const uint32_t* bhp = &kh[nt >> 1][(nt & 1) * 2];
                    const uint32_t* blp = &kl[nt >> 1][(nt & 1) * 2];
                    mma_bf16(s[mt][nt], qfh[mt][kd], bhp);
                    mma_bf16(s[mt][nt], qfh[mt][kd], blp);
                    mma_bf16(s[mt][nt], qfl[mt][kd], bhp);
                }
        }

        // causal mask — only diagonal-band tiles need the pass at all
        if ((k0 + FK - 1) > (q0 + wid * 32)) {
#pragma unroll
            for (int mt = 0; mt < 2; mt++)
#pragma unroll
                for (int nt = 0; nt < 8; nt++)
#pragma unroll
                    for (int c = 0; c < 4; c++) {
                        int row = q0 + wid * 32 + mt * 16 + (lid >> 2) + ((c >> 1) << 3);
                        int key = k0 + nt * 8 + 2 * (lid & 3) + (c & 1);
                        if (key > row) s[mt][nt][c] = -1e30f;
                    }
        }

#pragma unroll
        for (int mt = 0; mt < 2; mt++)
#pragma unroll
            for (int hf = 0; hf < 2; hf++) {
                const int ri = mt * 2 + hf;
                float mx = -1e30f;
#pragma unroll
                for (int nt = 0; nt < 8; nt++) {
                    mx = fmaxf(mx, s[mt][nt][hf * 2]);
                    mx = fmaxf(mx, s[mt][nt][hf * 2 + 1]);
                }
                mx = fmaxf(mx, __shfl_xor_sync(0xffffffff, mx, 1));
                mx = fmaxf(mx, __shfl_xor_sync(0xffffffff, mx, 2));
                float mnew = fmaxf(mrow[ri], mx);
                float corr = fast_exp2(mrow[ri] - mnew);
                mrow[ri] = mnew;
                float lsum = 0.0f;
#pragma unroll
                for (int nt = 0; nt < 8; nt++) {
                    float p0 = fast_exp2(s[mt][nt][hf * 2] - mnew);
                    float p1 = fast_exp2(s[mt][nt][hf * 2 + 1] - mnew);
                    s[mt][nt][hf * 2] = p0;
                    s[mt][nt][hf * 2 + 1] = p1;
                    lsum += p0 + p1;
                }
                lrow[ri] = lrow[ri] * corr + lsum;   // per-lane partial
#pragma unroll
                for (int dt = 0; dt < 8; dt++) {
                    o[mt][dt][hf * 2] *= corr;
                    o[mt][dt][hf * 2 + 1] *= corr;
                }
            }

        // ---- O += P V : P hi/lo compensated (3-term), cvt2-packed ----
#pragma unroll
        for (int kk = 0; kk < 4; kk++) {
            uint32_t ph[2][4], pl[2][4];
#pragma unroll
            for (int mt = 0; mt < 2; mt++) {
#pragma unroll
                for (int half = 0; half < 2; half++) {
                    float p0 = s[mt][2 * kk + half][0], p1 = s[mt][2 * kk + half][1];
                    float p2 = s[mt][2 * kk + half][2], p3 = s[mt][2 * kk + half][3];
                    uint32_t h01 = cvt2_bf16(p0, p1);
                    uint32_t h23 = cvt2_bf16(p2, p3);
                    ph[mt][half * 2 + 0] = h01;
                    ph[mt][half * 2 + 1] = h23;
                    pl[mt][half * 2 + 0] =
                        cvt2_bf16(p0 - bf_lo_f(h01), p1 - bf_hi_f(h01));
                    pl[mt][half * 2 + 1] =
                        cvt2_bf16(p2 - bf_lo_f(h23), p3 - bf_hi_f(h23));
                }
            }
            uint32_t vh[4][4], vl[4][4];
#pragma unroll
            for (int dp = 0; dp < 4; dp++) {
                uint32_t off = SWZ((uint32_t)(
                    (kk * 16 + (qq & 1) * 8 + rin) * 128 + dp * 32 + (qq >> 1) * 16));
                ldsm4t(vh[dp], stb + 16384 + off);
                ldsm4t(vl[dp], stb + 24576 + off);
            }
#pragma unroll
            for (int mt = 0; mt < 2; mt++)
#pragma unroll
                for (int dt = 0; dt < 8; dt++) {
                    const uint32_t* bhp = &vh[dt >> 1][(dt & 1) * 2];
                    const uint32_t* blp = &vl[dt >> 1][(dt & 1) * 2];
                    mma_bf16(o[mt][dt], ph[mt], bhp);
                    mma_bf16(o[mt][dt], ph[mt], blp);
                    mma_bf16(o[mt][dt], pl[mt], bhp);
                }
        }
        __syncthreads();
    }

    // ---- final: reduce deferred l across the 4-lane group, normalize ----
    float inv[4];
#pragma unroll
    for (int ri = 0; ri < 4; ri++) {
        float l = lrow[ri];
        l += __shfl_xor_sync(0xffffffff, l, 1);
        l += __shfl_xor_sync(0xffffffff, l, 2);
        inv[ri] = 1.0f / l;
    }

#pragma unroll
    for (int mt = 0; mt < 2; mt++)
#pragma unroll
        for (int dt = 0; dt < 8; dt++) {
            int col = h * 64 + dt * 8 + 2 * (lid & 3);
#pragma unroll
            for (int hf = 0; hf < 2; hf++) {
                int row = q0 + wid * 32 + mt * 16 + (lid >> 2) + hf * 8;
                float v0 = o[mt][dt][hf * 2] * inv[mt * 2 + hf];
                float v1 = o[mt][dt][hf * 2 + 1] * inv[mt * 2 + hf];
                size_t idx = ((size_t)(b * SS + row)) * EE + col;
                uint32_t h01 = cvt2_bf16(v0, v1);
                *reinterpret_cast<uint32_t*>(ohi + idx) = h01;
                *reinterpret_cast<uint32_t*>(olo + idx) =
                    cvt2_bf16(v0 - bf_lo_f(h01), v1 - bf_hi_f(h01));
            }
        }
}

// ---------------------------------------------------------------------------
// Launch
// ---------------------------------------------------------------------------
extern "C" void kernel_launch(void* const* d_in, const int* in_sizes, int n_in,
                              void* d_out, int out_size) {
    const float* x  = (const float*)d_in[0];
    const float* Wq = (const float*)d_in[1];
    const float* Wk = (const float*)d_in[2];
    const float* Wv = (const float*)d_in[3];
    const float* Wo = (const float*)d_in[4];
    float* out = (float*)d_out;

    __nv_bfloat16 *ahi, *alo, *whi, *wlo, *qhi, *qlo, *khi, *klo, *vhi, *vlo;
    cudaGetSymbolAddress((void**)&ahi, g_ahi);
    cudaGetSymbolAddress((void**)&alo, g_alo);
    cudaGetSymbolAddress((void**)&whi, g_whi);
    cudaGetSymbolAddress((void**)&wlo, g_wlo);
    cudaGetSymbolAddress((void**)&qhi, g_qhi);
    cudaGetSymbolAddress((void**)&qlo, g_qlo);
    cudaGetSymbolAddress((void**)&khi, g_khi);
    cudaGetSymbolAddress((void**)&klo, g_klo);
    cudaGetSymbolAddress((void**)&vhi, g_vhi);
    cudaGetSymbolAddress((void**)&vlo, g_vlo);

    cudaFuncSetAttribute(gemm_mma, cudaFuncAttributeMaxDynamicSharedMemorySize,
                         GEMM_SMEM);
    cudaFuncSetAttribute(gemm_mma64, cudaFuncAttributeMaxDynamicSharedMemorySize,
                         GEMM64_SMEM);
    cudaFuncSetAttribute(flash_mma, cudaFuncAttributeMaxDynamicSharedMemorySize,
                         FLASH_SMEM);

    rope_table_kernel<<<64, 1024>>>();
    split_x_kernel<<<(MROWS * EE / 4 + 255) / 256, 256>>>(x, ahi, alo, MROWS * EE / 4);
    split_w_kernel<<<(4 * NW / 4 + 255) / 256, 256>>>(Wq, Wk, Wv, Wo, whi, wlo);

    // Persistent fused QKV GEMMs (444 CTAs loop over 1536 tiles)
    gemm_mma<<<QKV_GRID, 128, GEMM_SMEM>>>(ahi, alo, whi, wlo,
                                           qhi, qlo, khi, klo, vhi, vlo);

    dim3 fg(SS / FQ, BB * HH);         // (16, 32)
    flash_mma<<<fg, 128, FLASH_SMEM>>>(qhi, qlo, khi, klo, vhi, vlo, ahi, alo);

    // Persistent output projection (592 CTAs over 1024 tiles)
    gemm_mma64<<<WO_GRID, 128, GEMM64_SMEM>>>(ahi, alo, whi + 3 * (size_t)NW,
                                              wlo + 3 * (size_t)NW, out);
}

// round 15
// speedup vs baseline: 1.0462x; 1.0462x over previous
#include <cuda_runtime.h>
#include <cuda_bf16.h>
#include <math.h>
#include <stdint.h>

// Problem constants
#define BB 2
#define SS 2048
#define EE 1024
#define HH 16
#define DD 64
#define MROWS (BB * SS)   // 4096
#define NW (EE * EE)      // 1048576

// Scratch (__device__ globals; allocation-free rule)
__device__ __nv_bfloat16 g_ahi[MROWS * EE];
__device__ __nv_bfloat16 g_alo[MROWS * EE];
__device__ __nv_bfloat16 g_whi[4 * NW];
__device__ __nv_bfloat16 g_wlo[4 * NW];
__device__ __nv_bfloat16 g_qhi[MROWS * EE];
__device__ __nv_bfloat16 g_qlo[MROWS * EE];
__device__ __nv_bfloat16 g_khi[MROWS * EE];
__device__ __nv_bfloat16 g_klo[MROWS * EE];
__device__ __nv_bfloat16 g_vhi[MROWS * EE];
__device__ __nv_bfloat16 g_vlo[MROWS * EE];
__device__ float2 g_rope[SS * 32];

// ---------------------------------------------------------------------------
// Helpers
// ---------------------------------------------------------------------------
static __device__ __forceinline__ uint32_t smem_u32(const void* p) {
    uint32_t a;
    asm("{ .reg .u64 t; cvta.to.shared.u64 t, %1; cvt.u32.u64 %0, t; }"
        : "=r"(a) : "l"(p));
    return a;
}

#define SWZ(o)   ((o) ^ (((o) >> 3) & 0x70))
#define SWZ64(o) ((o) ^ (((o) >> 3) & 0x30))

static __device__ __forceinline__ void cp16(uint32_t saddr, const void* g) {
    asm volatile("cp.async.cg.shared.global [%0], [%1], 16;"
                 :: "r"(saddr), "l"(g));
}
#define CP_COMMIT() asm volatile("cp.async.commit_group;")
#define CP_WAIT(n)  asm volatile("cp.async.wait_group %0;" :: "n"(n))

static __device__ __forceinline__ void ldsm4(uint32_t* r, uint32_t addr) {
    asm volatile("ldmatrix.sync.aligned.m8n8.x4.shared.b16 {%0,%1,%2,%3}, [%4];"
                 : "=r"(r[0]), "=r"(r[1]), "=r"(r[2]), "=r"(r[3]) : "r"(addr));
}

static __device__ __forceinline__ void ldsm4t(uint32_t* r, uint32_t addr) {
    asm volatile("ldmatrix.sync.aligned.m8n8.x4.trans.shared.b16 {%0,%1,%2,%3}, [%4];"
                 : "=r"(r[0]), "=r"(r[1]), "=r"(r[2]), "=r"(r[3]) : "r"(addr));
}

static __device__ __forceinline__ void mma_bf16(float* c, const uint32_t* a,
                                                const uint32_t* b) {
    asm volatile(
        "mma.sync.aligned.m16n8k16.row.col.f32.bf16.bf16.f32 "
        "{%0,%1,%2,%3}, {%4,%5,%6,%7}, {%8,%9}, {%0,%1,%2,%3};"
        : "+f"(c[0]), "+f"(c[1]), "+f"(c[2]), "+f"(c[3])
        : "r"(a[0]), "r"(a[1]), "r"(a[2]), "r"(a[3]), "r"(b[0]), "r"(b[1]));
}

// One-instruction pack of two floats into bf16x2 (lo -> low half)
static __device__ __forceinline__ uint32_t cvt2_bf16(float lo, float hi) {
    uint32_t r;
    asm("cvt.rn.bf16x2.f32 %0, %1, %2;" : "=r"(r) : "f"(hi), "f"(lo));
    return r;
}
static __device__ __forceinline__ float bf_lo_f(uint32_t p) {
    return __int_as_float(p << 16);
}
static __device__ __forceinline__ float bf_hi_f(uint32_t p) {
    return __int_as_float(p & 0xFFFF0000u);
}

// FFMA-only 2^x (input already in log2 domain)
static __device__ __forceinline__ float fast_exp2(float x) {
    x = fmaxf(x, -126.0f);
    float fn = x + 12582912.0f;
    int n = __float_as_int(fn) - 0x4B400000;
    float f = x - (fn - 12582912.0f);
    float r = 0.0013333558f;
    r = fmaf(r, f, 0.0096181291f);
    r = fmaf(r, f, 0.0555041087f);
    r = fmaf(r, f, 0.2402265069f);
    r = fmaf(r, f, 0.6931471806f);
    r = fmaf(r, f, 1.0f);
    return __int_as_float(__float_as_int(r) + (n << 23));
}

// score pre-scale folded into Q: log2(e)/32
#define QSCALE 0.045084441f

// ---------------------------------------------------------------------------
// Fused prelude: split x, split Wq..Wo, build rope table — one launch.
// ---------------------------------------------------------------------------
static __device__ __forceinline__ void split4_store(
    float4 v, __nv_bfloat16* hi, __nv_bfloat16* lo, size_t i4) {
    uint32_t h01 = cvt2_bf16(v.x, v.y);
    uint32_t h23 = cvt2_bf16(v.z, v.w);
    uint32_t l01 = cvt2_bf16(v.x - bf_lo_f(h01), v.y - bf_hi_f(h01));
    uint32_t l23 = cvt2_bf16(v.z - bf_lo_f(h23), v.w - bf_hi_f(h23));
    reinterpret_cast<uint2*>(hi)[i4] = make_uint2(h01, h23);
    reinterpret_cast<uint2*>(lo)[i4] = make_uint2(l01, l23);
}

#define NX4 (MROWS * EE / 4)      // 1048576
#define NW4 (4 * NW / 4)          // 1048576
#define NROPE (SS * 32)           // 65536
#define PRELUDE_N (NX4 + NW4 + NROPE)

__global__ void prelude_kernel(const float* __restrict__ x,
                               const float* __restrict__ w0,
                               const float* __restrict__ w1,
                               const float* __restrict__ w2,
                               const float* __restrict__ w3,
                               __nv_bfloat16* __restrict__ ahi,
                               __nv_bfloat16* __restrict__ alo,
                               __nv_bfloat16* __restrict__ whi,
                               __nv_bfloat16* __restrict__ wlo) {
    int i = blockIdx.x * blockDim.x + threadIdx.x;
    if (i < NX4) {
        split4_store(reinterpret_cast<const float4*>(x)[i], ahi, alo, i);
    } else if (i < NX4 + NW4) {
        int j = i - NX4;
        int z = j >> 18;                 // NW/4 = 262144 = 2^18
        int loc = j & 0x3FFFF;
        const float* w = (z == 0) ? w0 : (z == 1) ? w1 : (z == 2) ? w2 : w3;
        split4_store(reinterpret_cast<const float4*>(w)[loc], whi, wlo, j);
    } else if (i < PRELUDE_N) {
        int j = i - NX4 - NW4;
        int s = j >> 5, ii = j & 31;
        float theta = expf(-logf(10000.0f) * (2.0f * (float)ii) / 64.0f);
        float c, sn;
        sincosf((float)s * theta, &sn, &c);
        g_rope[j] = make_float2(c, sn);
    }
}

// ---------------------------------------------------------------------------
// Warp-MMA GEMM (QKV, round-13 proven): CTA 128x64, 4 warps (warp 64x32),
// BK=32, 3-stage cp.async, SW64. grid (16,32,3).
// ---------------------------------------------------------------------------
#define BM 128
#define BN 64
#define BK 32
#define KTILES (EE / BK)                 // 32
#define A_T (BM * BK * 2)                // 8192
#define B_T (BN * BK * 2)                // 4096
#define STAGE_B (2 * A_T + 2 * B_T)      // 24576
#define GEMM_SMEM (3 * STAGE_B)          // 73728

__global__ void __launch_bounds__(128, 3) gemm_mma(
    const __nv_bfloat16* __restrict__ Ahi, const __nv_bfloat16* __restrict__ Alo,
    const __nv_bfloat16* __restrict__ Whi, const __nv_bfloat16* __restrict__ Wlo,
    __nv_bfloat16* __restrict__ qhi, __nv_bfloat16* __restrict__ qlo,
    __nv_bfloat16* __restrict__ khi, __nv_bfloat16* __restrict__ klo,
    __nv_bfloat16* __restrict__ vhi, __nv_bfloat16* __restrict__ vlo) {
    extern __shared__ __align__(1024) char smem[];
    const uint32_t sb = smem_u32(smem);

    const int tid = threadIdx.x;
    const int wid = tid >> 5;
    const int lid = tid & 31;
    const int row0 = blockIdx.y * BM;
    const int col0 = blockIdx.x * BN;
    const int wm = wid & 1;
    const int wn = wid >> 1;              // 0..1
    const int z = blockIdx.z;

    const __nv_bfloat16* Bhi = Whi + (size_t)z * NW;
    const __nv_bfloat16* Blo = Wlo + (size_t)z * NW;

    const int O_AHI = 0, O_ALO = A_T, O_BHI = 2 * A_T, O_BLO = 2 * A_T + B_T;

    float acc[4][4][4] = {};

    auto load_tiles = [&](int st, int kt) {
        const uint32_t stb = sb + st * STAGE_B;
        const int k0 = kt * BK;
#pragma unroll
        for (int i = 0; i < 4; i++) {
            int c = tid + i * 128;        // 0..511
            int r = c >> 2;               // 0..127
            int cb = (c & 3) * 16;
            uint32_t so = SWZ64((uint32_t)(r * 64 + cb));
            size_t ga = (size_t)(row0 + r) * EE + k0 + (c & 3) * 8;
            cp16(stb + O_AHI + so, Ahi + ga);
            cp16(stb + O_ALO + so, Alo + ga);
        }
#pragma unroll
        for (int i = 0; i < 2; i++) {
            int c = tid + i * 128;        // 0..255
            int r = c >> 2;               // 0..63
            int cb = (c & 3) * 16;
            uint32_t so = SWZ64((uint32_t)(r * 64 + cb));
            size_t gb = (size_t)(col0 + r) * EE + k0 + (c & 3) * 8;
            cp16(stb + O_BHI + so, Bhi + gb);
            cp16(stb + O_BLO + so, Blo + gb);
        }
    };

    load_tiles(0, 0);
    CP_COMMIT();
    load_tiles(1, 1);
    CP_COMMIT();

    const int q = lid >> 3, rin = lid & 7;

    for (int kt = 0; kt < KTILES; kt++) {
        if (kt < KTILES - 1) { CP_WAIT(1); } else { CP_WAIT(0); }
        __syncthreads();
        if (kt + 2 < KTILES) {
            int st = kt + 2;
            st = st - (st / 3) * 3;
            load_tiles(st, kt + 2);
            CP_COMMIT();
        }

        const int cur = kt - (kt / 3) * 3;
        const uint32_t stb = sb + cur * STAGE_B;

#pragma unroll
        for (int ks = 0; ks < 2; ks++) {
            const int kb = ks * 32;
            uint32_t ahi[4][4], alo[4][4], bhi[2][4], blo[2][4];
#pragma unroll
            for (int mt = 0; mt < 4; mt++) {
                uint32_t off = SWZ64((uint32_t)(
                    (wm * 64 + mt * 16 + (q & 1) * 8 + rin) * 64 + kb + (q >> 1) * 16));
                ldsm4(ahi[mt], stb + O_AHI + off);
                ldsm4(alo[mt], stb + O_ALO + off);
            }
#pragma unroll
            for (int p = 0; p < 2; p++) {
                uint32_t off = SWZ64((uint32_t)(
                    (wn * 32 + p * 16 + (q >> 1) * 8 + rin) * 64 + kb + (q & 1) * 16));
                ldsm4(bhi[p], stb + O_BHI + off);
                ldsm4(blo[p], stb + O_BLO + off);
            }
#pragma unroll
            for (int mt = 0; mt < 4; mt++)
#pragma unroll
                for (int nt = 0; nt < 4; nt++) {
                    const uint32_t* bh = &bhi[nt >> 1][(nt & 1) * 2];
                    const uint32_t* bl = &blo[nt >> 1][(nt & 1) * 2];
                    mma_bf16(acc[mt][nt], ahi[mt], bh);
                    mma_bf16(acc[mt][nt], ahi[mt], bl);
                    mma_bf16(acc[mt][nt], alo[mt], bh);
                }
        }
    }

    const int r_base = row0 + wm * 64 + (lid >> 2);
    const int c_base = col0 + wn * 32 + (lid & 3) * 2;

    __nv_bfloat16* Dhi = (z == 0) ? qhi : (z == 1) ? khi : vhi;
    __nv_bfloat16* Dlo = (z == 0) ? qlo : (z == 1) ? klo : vlo;
    const int mode = (z == 2) ? 2 : 1;
    const float qs = (z == 0) ? QSCALE : 1.0f;
#pragma unroll
    for (int mt = 0; mt < 4; mt++)
#pragma unroll
        for (int nt = 0; nt < 4; nt++) {
            int gr = r_base + mt * 16;
            int gc = c_base + nt * 8;
            int hh = gc >> 6, d = gc & 63, ii = d >> 1;
            int b_ = gr >> 11;
            int s1 = gr & (SS - 1);
            int s2 = (gr + 8) & (SS - 1);
            float v0 = acc[mt][nt][0], v1 = acc[mt][nt][1];
            float v2 = acc[mt][nt][2], v3 = acc[mt][nt][3];
            if (mode == 1) {
                float2 cs1 = g_rope[(s1 << 5) + ii];
                float2 cs2 = g_rope[(s2 << 5) + ii];
                float t0 = v0 * cs1.x - v1 * cs1.y;
                v1 = (v0 * cs1.y + v1 * cs1.x) * qs; v0 = t0 * qs;
                t0 = v2 * cs2.x - v3 * cs2.y;
                v3 = (v2 * cs2.y + v3 * cs2.x) * qs; v2 = t0 * qs;
            }
            size_t o1 = ((size_t)((b_ * HH + hh) * SS + s1)) * 64 + d;
            size_t o2 = ((size_t)((b_ * HH + hh) * SS + s2)) * 64 + d;
            uint32_t h01 = cvt2_bf16(v0, v1);
            uint32_t h23 = cvt2_bf16(v2, v3);
            *reinterpret_cast<uint32_t*>(Dhi + o1) = h01;
            *reinterpret_cast<uint32_t*>(Dhi + o2) = h23;
            *reinterpret_cast<uint32_t*>(Dlo + o1) =
                cvt2_bf16(v0 - bf_lo_f(h01), v1 - bf_hi_f(h01));
            *reinterpret_cast<uint32_t*>(Dlo + o2) =
                cvt2_bf16(v2 - bf_lo_f(h23), v3 - bf_hi_f(h23));
        }
}

// ---------------------------------------------------------------------------
// Wo GEMM (round-13 proven): CTA 64x64, 4 warps (warp 32x32), BK=32, 3-stage.
// fp32 output. grid (16, 64).
// ---------------------------------------------------------------------------
#define BM2 64
#define BN2 64
#define A2_T (BM2 * BK * 2)              // 4096
#define B2_T (BN2 * BK * 2)              // 4096
#define STAGE2 (2 * A2_T + 2 * B2_T)     // 16384
#define GEMM64_SMEM (3 * STAGE2)         // 49152

__global__ void __launch_bounds__(128, 4) gemm_mma64(
    const __nv_bfloat16* __restrict__ Ahi, const __nv_bfloat16* __restrict__ Alo,
    const __nv_bfloat16* __restrict__ Bhi, const __nv_bfloat16* __restrict__ Blo,
    float* __restrict__ C) {
    extern __shared__ __align__(1024) char smem[];
    const uint32_t sb = smem_u32(smem);

    const int tid = threadIdx.x;
    const int wid = tid >> 5;
    const int lid = tid & 31;
    const int row0 = blockIdx.y * BM2;
    const int col0 = blockIdx.x * BN2;
    const int wm = wid & 1;
    const int wn = wid >> 1;              // 0..1

    const int O_AHI = 0, O_ALO = A2_T, O_BHI = 2 * A2_T, O_BLO = 2 * A2_T + B2_T;

    float acc[2][4][4] = {};

    auto load_tiles = [&](int st, int kt) {
        const uint32_t stb = sb + st * STAGE2;
        const int k0 = kt * BK;
#pragma unroll
        for (int i = 0; i < 2; i++) {
            int c = tid + i * 128;        // 0..255
            int r = c >> 2;               // 0..63
            int cb = (c & 3) * 16;
            uint32_t so = SWZ64((uint32_t)(r * 64 + cb));
            size_t ga = (size_t)(row0 + r) * EE + k0 + (c & 3) * 8;
            cp16(stb + O_AHI + so, Ahi + ga);
            cp16(stb + O_ALO + so, Alo + ga);
            size_t gb = (size_t)(col0 + r) * EE + k0 + (c & 3) * 8;
            cp16(stb + O_BHI + so, Bhi + gb);
            cp16(stb + O_BLO + so, Blo + gb);
        }
    };

    load_tiles(0, 0);
    CP_COMMIT();
    load_tiles(1, 1);
    CP_COMMIT();

    const int q = lid >> 3, rin = lid & 7;

    for (int kt = 0; kt < KTILES; kt++) {
        if (kt < KTILES - 1) { CP_WAIT(1); } else { CP_WAIT(0); }
        __syncthreads();
        if (kt + 2 < KTILES) {
            int st = kt + 2;
            st = st - (st / 3) * 3;
            load_tiles(st, kt + 2);
            CP_COMMIT();
        }

        const int cur = kt - (kt / 3) * 3;
        const uint32_t stb = sb + cur * STAGE2;

#pragma unroll
        for (int ks = 0; ks < 2; ks++) {
            const int kb = ks * 32;
            uint32_t ahi[2][4], alo[2][4], bhi[2][4], blo[2][4];
#pragma unroll
            for (int mt = 0; mt < 2; mt++) {
                uint32_t off = SWZ64((uint32_t)(
                    (wm * 32 + mt * 16 + (q & 1) * 8 + rin) * 64 + kb + (q >> 1) * 16));
                ldsm4(ahi[mt], stb + O_AHI + off);
                ldsm4(alo[mt], stb + O_ALO + off);
            }
#pragma unroll
            for (int p = 0; p < 2; p++) {
                uint32_t off = SWZ64((uint32_t)(
                    (wn * 32 + p * 16 + (q >> 1) * 8 + rin) * 64 + kb + (q & 1) * 16));
                ldsm4(bhi[p], stb + O_BHI + off);
                ldsm4(blo[p], stb + O_BLO + off);
            }
#pragma unroll
            for (int mt = 0; mt < 2; mt++)
#pragma unroll
                for (int nt = 0; nt < 4; nt++) {
                    const uint32_t* bh = &bhi[nt >> 1][(nt & 1) * 2];
                    const uint32_t* bl = &blo[nt >> 1][(nt & 1) * 2];
                    mma_bf16(acc[mt][nt], ahi[mt], bh);
                    mma_bf16(acc[mt][nt], ahi[mt], bl);
                    mma_bf16(acc[mt][nt], alo[mt], bh);
                }
        }
    }

    const int r_base = row0 + wm * 32 + (lid >> 2);
    const int c_base = col0 + wn * 32 + (lid & 3) * 2;
#pragma unroll
    for (int mt = 0; mt < 2; mt++)
#pragma unroll
        for (int nt = 0; nt < 4; nt++) {
            int r = r_base + mt * 16;
            int c = c_base + nt * 8;
            *reinterpret_cast<float2*>(C + (size_t)r * EE + c) =
                make_float2(acc[mt][nt][0], acc[mt][nt][1]);
            *reinterpret_cast<float2*>(C + (size_t)(r + 8) * EE + c) =
                make_float2(acc[mt][nt][2], acc[mt][nt][3]);
        }
}

// ---------------------------------------------------------------------------
// Warp-MMA causal flash attention. Q fragments in registers; 3-stage KV ring
// (one barrier per tile, deeper prefetch).
// ---------------------------------------------------------------------------
#define FQ 128
#define FK 64
#define KV_STAGE 32768
#define FLASH_SMEM (3 * KV_STAGE)   // 98304

__global__ void __launch_bounds__(128, 2) flash_mma(
    const __nv_bfloat16* __restrict__ qhi, const __nv_bfloat16* __restrict__ qlo,
    const __nv_bfloat16* __restrict__ khi, const __nv_bfloat16* __restrict__ klo,
    const __nv_bfloat16* __restrict__ vhi, const __nv_bfloat16* __restrict__ vlo,
    __nv_bfloat16* __restrict__ ohi, __nv_bfloat16* __restrict__ olo) {
    extern __shared__ __align__(1024) char smem[];
    const uint32_t sb = smem_u32(smem);
    const int tid = threadIdx.x;
    const int wid = tid >> 5;
    const int lid = tid & 31;
    const int bh = blockIdx.y;
    const int qt = gridDim.x - 1 - blockIdx.x;
    const int q0 = qt * FQ;
    const int b = bh >> 4, h = bh & 15;
    const int qq = lid >> 3, rin = lid & 7;

    // ---- stage Q through stage-0 smem, capture fragments in registers ----
#pragma unroll
    for (int i = 0; i < 8; i++) {
        int c = i * 128 + tid;
        int r = c >> 3, cb = c & 7;
        uint32_t so = SWZ((uint32_t)(r * 128 + cb * 16));
        size_t g = ((size_t)bh * SS + q0 + r) * 64 + cb * 8;
        cp16(sb + so, qhi + g);
        cp16(sb + 16384 + so, qlo + g);
    }
    CP_COMMIT();
    CP_WAIT(0);
    __syncthreads();

    uint32_t qfh[2][4][4], qfl[2][4][4];
#pragma unroll
    for (int mt = 0; mt < 2; mt++)
#pragma unroll
        for (int kd = 0; kd < 4; kd++) {
            uint32_t off = SWZ((uint32_t)(
                (wid * 32 + mt * 16 + (qq & 1) * 8 + rin) * 128 +
                kd * 32 + (qq >> 1) * 16));
            ldsm4(qfh[mt][kd], sb + off);
            ldsm4(qfl[mt][kd], sb + 16384 + off);
        }
    __syncthreads();   // all warps done reading Q staging before KV reuses it

    auto load_kv = [&](int st, int kt) {
        const uint32_t stb = sb + st * KV_STAGE;
        const size_t rb = (size_t)bh * SS + (size_t)kt * FK;
#pragma unroll
        for (int i = 0; i < 4; i++) {
            int c = i * 128 + tid;
            int r = c >> 3, cb = c & 7;
            uint32_t so = SWZ((uint32_t)(r * 128 + cb * 16));
            size_t g = (rb + r) * 64 + cb * 8;
            cp16(stb + so,         khi + g);
            cp16(stb + 8192 + so,  klo + g);
            cp16(stb + 16384 + so, vhi + g);
            cp16(stb + 24576 + so, vlo + g);
        }
    };

    float o[2][8][4] = {};
    float mrow[4] = {-1e30f, -1e30f, -1e30f, -1e30f};
    float lrow[4] = {};   // per-lane partials; cross-lane reduce at end

    const int nkt = 2 * qt + 2;   // always >= 2
    load_kv(0, 0);
    CP_COMMIT();
    load_kv(1, 1);
    CP_COMMIT();

    int cur = 0;   // kt % 3 tracked incrementally

    for (int kt = 0; kt < nkt; kt++) {
        if (kt < nkt - 1) { CP_WAIT(1); } else { CP_WAIT(0); }
        __syncthreads();
        if (kt + 2 < nkt) {
            int st = cur + 2;
            if (st >= 3) st -= 3;
            load_kv(st, kt + 2);
            CP_COMMIT();
        }

        const uint32_t stb = sb + cur * KV_STAGE;
        cur++;
        if (cur == 3) cur = 0;
        const int k0 = kt * FK;

        float s[2][8][4] = {};
#pragma unroll
        for (int kd = 0; kd < 4; kd++) {
            uint32_t kh[4][4], kl[4][4];
#pragma unroll
            for (int p = 0; p < 4; p++) {
                uint32_t off = SWZ((uint32_t)(
                    (p * 16 + (qq >> 1) * 8 + rin) * 128 + kd * 32 + (qq & 1) * 16));
                ldsm4(kh[p], stb + off);
                ldsm4(kl[p], stb + 8192 + off);
            }
#pragma unroll
            for (int mt = 0; mt < 2; mt++)
#pragma unroll
                for (int nt = 0; nt < 8; nt++) {
                    const uint32_t* bhp = &kh[nt >> 1][(nt & 1) * 2];
                    const uint32_t* blp = &kl[nt >> 1][(nt & 1) * 2];
                    mma_bf16(s[mt][nt], qfh[mt][kd], bhp);
                    mma_bf16(s[mt][nt], qfh[mt][kd], blp);
                    mma_bf16(s[mt][nt], qfl[mt][kd], bhp);
                }
        }

        // causal mask — only diagonal-band tiles need the pass at all
        if ((k0 + FK - 1) > (q0 + wid * 32)) {
#pragma unroll
            for (int mt = 0; mt < 2; mt++)
#pragma unroll
                for (int nt = 0; nt < 8; nt++)
#pragma unroll
                    for (int c = 0; c < 4; c++) {
                        int row = q0 + wid * 32 + mt * 16 + (lid >> 2) + ((c >> 1) << 3);
                        int key = k0 + nt * 8 + 2 * (lid & 3) + (c & 1);
                        if (key > row) s[mt][nt][c] = -1e30f;
                    }
        }

#pragma unroll
        for (int mt = 0; mt < 2; mt++)
#pragma unroll
            for (int hf = 0; hf < 2; hf++) {
                const int ri = mt * 2 + hf;
                float mx = -1e30f;
#pragma unroll
                for (int nt = 0; nt < 8; nt++) {
                    mx = fmaxf(mx, s[mt][nt][hf * 2]);
                    mx = fmaxf(mx, s[mt][nt][hf * 2 + 1]);
                }
                mx = fmaxf(mx, __shfl_xor_sync(0xffffffff, mx, 1));
                mx = fmaxf(mx, __shfl_xor_sync(0xffffffff, mx, 2));
                float mnew = fmaxf(mrow[ri], mx);
                float corr = fast_exp2(mrow[ri] - mnew);
                mrow[ri] = mnew;
                float lsum = 0.0f;
#pragma unroll
                for (int nt = 0; nt < 8; nt++) {
                    float p0 = fast_exp2(s[mt][nt][hf * 2] - mnew);
                    float p1 = fast_exp2(s[mt][nt][hf * 2 + 1] - mnew);
                    s[mt][nt][hf * 2] = p0;
                    s[mt][nt][hf * 2 + 1] = p1;
                    lsum += p0 + p1;
                }
                lrow[ri] = lrow[ri] * corr + lsum;   // per-lane partial
#pragma unroll
                for (int dt = 0; dt < 8; dt++) {
                    o[mt][dt][hf * 2] *= corr;
                    o[mt][dt][hf * 2 + 1] *= corr;
                }
            }

        // ---- O += P V : P hi/lo compensated (3-term), cvt2-packed ----
#pragma unroll
        for (int kk = 0; kk < 4; kk++) {
            uint32_t ph[2][4], pl[2][4];
#pragma unroll
            for (int mt = 0; mt < 2; mt++) {
#pragma unroll
                for (int half = 0; half < 2; half++) {
                    float p0 = s[mt][2 * kk + half][0], p1 = s[mt][2 * kk + half][1];
                    float p2 = s[mt][2 * kk + half][2], p3 = s[mt][2 * kk + half][3];
                    uint32_t h01 = cvt2_bf16(p0, p1);
                    uint32_t h23 = cvt2_bf16(p2, p3);
                    ph[mt][half * 2 + 0] = h01;
                    ph[mt][half * 2 + 1] = h23;
                    pl[mt][half * 2 + 0] =
                        cvt2_bf16(p0 - bf_lo_f(h01), p1 - bf_hi_f(h01));
                    pl[mt][half * 2 + 1] =
                        cvt2_bf16(p2 - bf_lo_f(h23), p3 - bf_hi_f(h23));
                }
            }
            uint32_t vh[4][4], vl[4][4];
#pragma unroll
            for (int dp = 0; dp < 4; dp++) {
                uint32_t off = SWZ((uint32_t)(
                    (kk * 16 + (qq & 1) * 8 + rin) * 128 + dp * 32 + (qq >> 1) * 16));
                ldsm4t(vh[dp], stb + 16384 + off);
                ldsm4t(vl[dp], stb + 24576 + off);
            }
#pragma unroll
            for (int mt = 0; mt < 2; mt++)
#pragma unroll
                for (int dt = 0; dt < 8; dt++) {
                    const uint32_t* bhp = &vh[dt >> 1][(dt & 1) * 2];
                    const uint32_t* blp = &vl[dt >> 1][(dt & 1) * 2];
                    mma_bf16(o[mt][dt], ph[mt], bhp);
                    mma_bf16(o[mt][dt], ph[mt], blp);
                    mma_bf16(o[mt][dt], pl[mt], bhp);
                }
        }
        // no trailing barrier: 3-stage ring — next iter's top barrier protects
    }

    // ---- final: reduce deferred l across the 4-lane group, normalize ----
    float inv[4];
#pragma unroll
    for (int ri = 0; ri < 4; ri++) {
        float l = lrow[ri];
        l += __shfl_xor_sync(0xffffffff, l, 1);
        l += __shfl_xor_sync(0xffffffff, l, 2);
        inv[ri] = 1.0f / l;
    }

#pragma unroll
    for (int mt = 0; mt < 2; mt++)
#pragma unroll
        for (int dt = 0; dt < 8; dt++) {
            int col = h * 64 + dt * 8 + 2 * (lid & 3);
#pragma unroll
            for (int hf = 0; hf < 2; hf++) {
                int row = q0 + wid * 32 + mt * 16 + (lid >> 2) + hf * 8;
                float v0 = o[mt][dt][hf * 2] * inv[mt * 2 + hf];
                float v1 = o[mt][dt][hf * 2 + 1] * inv[mt * 2 + hf];
                size_t idx = ((size_t)(b * SS + row)) * EE + col;
                uint32_t h01 = cvt2_bf16(v0, v1);
                *reinterpret_cast<uint32_t*>(ohi + idx) = h01;
                *reinterpret_cast<uint32_t*>(olo + idx) =
                    cvt2_bf16(v0 - bf_lo_f(h01), v1 - bf_hi_f(h01));
            }
        }
}

// ---------------------------------------------------------------------------
// Launch
// ---------------------------------------------------------------------------
extern "C" void kernel_launch(void* const* d_in, const int* in_sizes, int n_in,
                              void* d_out, int out_size) {
    const float* x  = (const float*)d_in[0];
    const float* Wq = (const float*)d_in[1];
    const float* Wk = (const float*)d_in[2];
    const float* Wv = (const float*)d_in[3];
    const float* Wo = (const float*)d_in[4];
    float* out = (float*)d_out;

    __nv_bfloat16 *ahi, *alo, *whi, *wlo, *qhi, *qlo, *khi, *klo, *vhi, *vlo;
    cudaGetSymbolAddress((void**)&ahi, g_ahi);
    cudaGetSymbolAddress((void**)&alo, g_alo);
    cudaGetSymbolAddress((void**)&whi, g_whi);
    cudaGetSymbolAddress((void**)&wlo, g_wlo);
    cudaGetSymbolAddress((void**)&qhi, g_qhi);
    cudaGetSymbolAddress((void**)&qlo, g_qlo);
    cudaGetSymbolAddress((void**)&khi, g_khi);
    cudaGetSymbolAddress((void**)&klo, g_klo);
    cudaGetSymbolAddress((void**)&vhi, g_vhi);
    cudaGetSymbolAddress((void**)&vlo, g_vlo);

    cudaFuncSetAttribute(gemm_mma, cudaFuncAttributeMaxDynamicSharedMemorySize,
                         GEMM_SMEM);
    cudaFuncSetAttribute(gemm_mma64, cudaFuncAttributeMaxDynamicSharedMemorySize,
                         GEMM64_SMEM);
    cudaFuncSetAttribute(flash_mma, cudaFuncAttributeMaxDynamicSharedMemorySize,
                         FLASH_SMEM);

    // Fused prelude: split x, split all 4 weights, build rope table
    prelude_kernel<<<(PRELUDE_N + 255) / 256, 256>>>(x, Wq, Wk, Wv, Wo,
                                                     ahi, alo, whi, wlo);

    // Fused QKV GEMMs (z selects weight slice + epilogue)
    dim3 gq(EE / BN, MROWS / BM, 3);   // (16, 32, 3)
    gemm_mma<<<gq, 128, GEMM_SMEM>>>(ahi, alo, whi, wlo,
                                     qhi, qlo, khi, klo, vhi, vlo);

    dim3 fg(SS / FQ, BB * HH);         // (16, 32)
    flash_mma<<<fg, 128, FLASH_SMEM>>>(qhi, qlo, khi, klo, vhi, vlo, ahi, alo);

    // Output projection: 64x64-tile GEMM (4 CTAs/SM)
    dim3 go(EE / BN2, MROWS / BM2);    // (16, 64)
    gemm_mma64<<<go, 128, GEMM64_SMEM>>>(ahi, alo, whi + 3 * (size_t)NW,
                                         wlo + 3 * (size_t)NW, out);
}

// round 17
// speedup vs baseline: 1.2012x; 1.1482x over previous
#include <cuda_runtime.h>
#include <cuda_bf16.h>
#include <cuda_fp16.h>
#include <math.h>
#include <stdint.h>

// Problem constants
#define BB 2
#define SS 2048
#define EE 1024
#define HH 16
#define DD 64
#define MROWS (BB * SS)   // 4096
#define NW (EE * EE)      // 1048576

// Scratch (__device__ globals; allocation-free rule)
__device__ __half g_xh[MROWS * EE];          // x as single fp16
__device__ __half g_wfh[3 * NW];             // Wq,Wk,Wv fp16 hi
__device__ __half g_wfl[3 * NW];             // Wq,Wk,Wv fp16 lo
__device__ __nv_bfloat16 g_whi[NW];          // Wo bf16 hi
__device__ __nv_bfloat16 g_wlo[NW];          // Wo bf16 lo
__device__ __nv_bfloat16 g_ahi[MROWS * EE];  // flash output hi
__device__ __nv_bfloat16 g_alo[MROWS * EE];  // flash output lo
__device__ __nv_bfloat16 g_qhi[MROWS * EE];
__device__ __nv_bfloat16 g_qlo[MROWS * EE];
__device__ __nv_bfloat16 g_khi[MROWS * EE];
__device__ __nv_bfloat16 g_klo[MROWS * EE];
__device__ __nv_bfloat16 g_vhi[MROWS * EE];
__device__ __nv_bfloat16 g_vlo[MROWS * EE];
__device__ float2 g_rope[SS * 32];

// ---------------------------------------------------------------------------
// Helpers
// ---------------------------------------------------------------------------
static __device__ __forceinline__ uint32_t smem_u32(const void* p) {
    uint32_t a;
    asm("{ .reg .u64 t; cvta.to.shared.u64 t, %1; cvt.u32.u64 %0, t; }"
        : "=r"(a) : "l"(p));
    return a;
}

#define SWZ(o)   ((o) ^ (((o) >> 3) & 0x70))
#define SWZ64(o) ((o) ^ (((o) >> 3) & 0x30))

static __device__ __forceinline__ void cp16(uint32_t saddr, const void* g) {
    asm volatile("cp.async.cg.shared.global [%0], [%1], 16;"
                 :: "r"(saddr), "l"(g));
}
#define CP_COMMIT() asm volatile("cp.async.commit_group;")
#define CP_WAIT(n)  asm volatile("cp.async.wait_group %0;" :: "n"(n))

static __device__ __forceinline__ void ldsm4(uint32_t* r, uint32_t addr) {
    asm volatile("ldmatrix.sync.aligned.m8n8.x4.shared.b16 {%0,%1,%2,%3}, [%4];"
                 : "=r"(r[0]), "=r"(r[1]), "=r"(r[2]), "=r"(r[3]) : "r"(addr));
}

static __device__ __forceinline__ void ldsm4t(uint32_t* r, uint32_t addr) {
    asm volatile("ldmatrix.sync.aligned.m8n8.x4.trans.shared.b16 {%0,%1,%2,%3}, [%4];"
                 : "=r"(r[0]), "=r"(r[1]), "=r"(r[2]), "=r"(r[3]) : "r"(addr));
}

static __device__ __forceinline__ void mma_bf16(float* c, const uint32_t* a,
                                                const uint32_t* b) {
    asm volatile(
        "mma.sync.aligned.m16n8k16.row.col.f32.bf16.bf16.f32 "
        "{%0,%1,%2,%3}, {%4,%5,%6,%7}, {%8,%9}, {%0,%1,%2,%3};"
        : "+f"(c[0]), "+f"(c[1]), "+f"(c[2]), "+f"(c[3])
        : "r"(a[0]), "r"(a[1]), "r"(a[2]), "r"(a[3]), "r"(b[0]), "r"(b[1]));
}

static __device__ __forceinline__ void mma_f16(float* c, const uint32_t* a,
                                               const uint32_t* b) {
    asm volatile(
        "mma.sync.aligned.m16n8k16.row.col.f32.f16.f16.f32 "
        "{%0,%1,%2,%3}, {%4,%5,%6,%7}, {%8,%9}, {%0,%1,%2,%3};"
        : "+f"(c[0]), "+f"(c[1]), "+f"(c[2]), "+f"(c[3])
        : "r"(a[0]), "r"(a[1]), "r"(a[2]), "r"(a[3]), "r"(b[0]), "r"(b[1]));
}

// One-instruction pack of two floats into bf16x2 (lo -> low half)
static __device__ __forceinline__ uint32_t cvt2_bf16(float lo, float hi) {
    uint32_t r;
    asm("cvt.rn.bf16x2.f32 %0, %1, %2;" : "=r"(r) : "f"(hi), "f"(lo));
    return r;
}
static __device__ __forceinline__ float bf_lo_f(uint32_t p) {
    return __int_as_float(p << 16);
}
static __device__ __forceinline__ float bf_hi_f(uint32_t p) {
    return __int_as_float(p & 0xFFFF0000u);
}

// pack two floats into f16x2 (lo -> low half)
static __device__ __forceinline__ uint32_t cvt2_f16(float lo, float hi) {
    uint32_t r;
    asm("cvt.rn.f16x2.f32 %0, %1, %2;" : "=r"(r) : "f"(hi), "f"(lo));
    return r;
}
static __device__ __forceinline__ float2 f16x2_to_f2(uint32_t p) {
    __half2 h = *reinterpret_cast<__half2*>(&p);
    return __half22float2(h);
}

// FFMA-only 2^x (input already in log2 domain)
static __device__ __forceinline__ float fast_exp2(float x) {
    x = fmaxf(x, -126.0f);
    float fn = x + 12582912.0f;
    int n = __float_as_int(fn) - 0x4B400000;
    float f = x - (fn - 12582912.0f);
    float r = 0.0013333558f;
    r = fmaf(r, f, 0.0096181291f);
    r = fmaf(r, f, 0.0555041087f);
    r = fmaf(r, f, 0.2402265069f);
    r = fmaf(r, f, 0.6931471806f);
    r = fmaf(r, f, 1.0f);
    return __int_as_float(__float_as_int(r) + (n << 23));
}

// score pre-scale folded into Q: log2(e)/32
#define QSCALE 0.045084441f

// ---------------------------------------------------------------------------
// Fused prelude: x -> fp16 single; Wq/Wk/Wv -> fp16 hi/lo; Wo -> bf16 hi/lo;
// rope table. One launch.
// ---------------------------------------------------------------------------
static __device__ __forceinline__ void split4_store_bf(
    float4 v, __nv_bfloat16* hi, __nv_bfloat16* lo, size_t i4) {
    uint32_t h01 = cvt2_bf16(v.x, v.y);
    uint32_t h23 = cvt2_bf16(v.z, v.w);
    uint32_t l01 = cvt2_bf16(v.x - bf_lo_f(h01), v.y - bf_hi_f(h01));
    uint32_t l23 = cvt2_bf16(v.z - bf_lo_f(h23), v.w - bf_hi_f(h23));
    reinterpret_cast<uint2*>(hi)[i4] = make_uint2(h01, h23);
    reinterpret_cast<uint2*>(lo)[i4] = make_uint2(l01, l23);
}

static __device__ __forceinline__ void split4_store_f16(
    float4 v, __half* hi, __half* lo, size_t i4) {
    uint32_t h01 = cvt2_f16(v.x, v.y);
    uint32_t h23 = cvt2_f16(v.z, v.w);
    float2 f01 = f16x2_to_f2(h01);
    float2 f23 = f16x2_to_f2(h23);
    uint32_t l01 = cvt2_f16(v.x - f01.x, v.y - f01.y);
    uint32_t l23 = cvt2_f16(v.z - f23.x, v.w - f23.y);
    reinterpret_cast<uint2*>(hi)[i4] = make_uint2(h01, h23);
    reinterpret_cast<uint2*>(lo)[i4] = make_uint2(l01, l23);
}

#define NX4 (MROWS * EE / 4)      // 1048576
#define NWF4 (3 * NW / 4)         // 786432
#define NWO4 (NW / 4)             // 262144
#define NROPE (SS * 32)           // 65536
#define PRELUDE_N (NX4 + NWF4 + NWO4 + NROPE)

__global__ void prelude_kernel(const float* __restrict__ x,
                               const float* __restrict__ w0,
                               const float* __restrict__ w1,
                               const float* __restrict__ w2,
                               const float* __restrict__ w3,
                               __half* __restrict__ xh,
                               __half* __restrict__ wfh,
                               __half* __restrict__ wfl,
                               __nv_bfloat16* __restrict__ whi,
                               __nv_bfloat16* __restrict__ wlo) {
    int i = blockIdx.x * blockDim.x + threadIdx.x;
    if (i < NX4) {
        float4 v = reinterpret_cast<const float4*>(x)[i];
        uint32_t h01 = cvt2_f16(v.x, v.y);
        uint32_t h23 = cvt2_f16(v.z, v.w);
        reinterpret_cast<uint2*>(xh)[i] = make_uint2(h01, h23);
    } else if (i < NX4 + NWF4) {
        int j = i - NX4;
        int z = j >> 18;                 // NW/4 = 2^18
        int loc = j & 0x3FFFF;
        const float* w = (z == 0) ? w0 : (z == 1) ? w1 : w2;
        split4_store_f16(reinterpret_cast<const float4*>(w)[loc], wfh, wfl, j);
    } else if (i < NX4 + NWF4 + NWO4) {
        int loc = i - NX4 - NWF4;
        split4_store_bf(reinterpret_cast<const float4*>(w3)[loc], whi, wlo, loc);
    } else if (i < PRELUDE_N) {
        int j = i - NX4 - NWF4 - NWO4;
        int s = j >> 5, ii = j & 31;
        float theta = expf(-logf(10000.0f) * (2.0f * (float)ii) / 64.0f);
        float c, sn;
        sincosf((float)s * theta, &sn, &c);
        g_rope[j] = make_float2(c, sn);
    }
}

// ---------------------------------------------------------------------------
// fp16 2-term QKV GEMM: C = x_f16 @ (Whi + Wlo)^T. CTA 128x64, 4 warps
// (warp 64x32), BK=32, 3-stage cp.async, SW64. grid (16,32,3).
// ---------------------------------------------------------------------------
#define BM 128
#define BN 64
#define BK 32
#define KTILES (EE / BK)                 // 32
#define AF_T (BM * BK * 2)               // 8192 (fp16)
#define BF_T (BN * BK * 2)               // 4096
#define STAGE_F (AF_T + 2 * BF_T)        // 16384
#define GEMM_SMEM (3 * STAGE_F)          // 49152

__global__ void __launch_bounds__(128, 3) gemm_qkv(
    const __half* __restrict__ Ah,
    const __half* __restrict__ Wfh, const __half* __restrict__ Wfl,
    __nv_bfloat16* __restrict__ qhi, __nv_bfloat16* __restrict__ qlo,
    __nv_bfloat16* __restrict__ khi, __nv_bfloat16* __restrict__ klo,
    __nv_bfloat16* __restrict__ vhi, __nv_bfloat16* __restrict__ vlo) {
    extern __shared__ __align__(1024) char smem[];
    const uint32_t sb = smem_u32(smem);

    const int tid = threadIdx.x;
    const int wid = tid >> 5;
    const int lid = tid & 31;
    const int row0 = blockIdx.y * BM;
    const int col0 = blockIdx.x * BN;
    const int wm = wid & 1;
    const int wn = wid >> 1;              // 0..1
    const int z = blockIdx.z;

    const __half* Bhi = Wfh + (size_t)z * NW;
    const __half* Blo = Wfl + (size_t)z * NW;

    const int O_A = 0, O_BHI = AF_T, O_BLO = AF_T + BF_T;

    float acc[4][4][4] = {};

    auto load_tiles = [&](int st, int kt) {
        const uint32_t stb = sb + st * STAGE_F;
        const int k0 = kt * BK;
#pragma unroll
        for (int i = 0; i < 4; i++) {
            int c = tid + i * 128;        // 0..511
            int r = c >> 2;               // 0..127
            int cb = (c & 3) * 16;
            uint32_t so = SWZ64((uint32_t)(r * 64 + cb));
            size_t ga = (size_t)(row0 + r) * EE + k0 + (c & 3) * 8;
            cp16(stb + O_A + so, Ah + ga);
        }
#pragma unroll
        for (int i = 0; i < 2; i++) {
            int c = tid + i * 128;        // 0..255
            int r = c >> 2;               // 0..63
            int cb = (c & 3) * 16;
            uint32_t so = SWZ64((uint32_t)(r * 64 + cb));
            size_t gb = (size_t)(col0 + r) * EE + k0 + (c & 3) * 8;
            cp16(stb + O_BHI + so, Bhi + gb);
            cp16(stb + O_BLO + so, Blo + gb);
        }
    };

    load_tiles(0, 0);
    CP_COMMIT();
    load_tiles(1, 1);
    CP_COMMIT();

    const int q = lid >> 3, rin = lid & 7;

    for (int kt = 0; kt < KTILES; kt++) {
        if (kt < KTILES - 1) { CP_WAIT(1); } else { CP_WAIT(0); }
        __syncthreads();
        if (kt + 2 < KTILES) {
            int st = kt + 2;
            st = st - (st / 3) * 3;
            load_tiles(st, kt + 2);
            CP_COMMIT();
        }

        const int cur = kt - (kt / 3) * 3;
        const uint32_t stb = sb + cur * STAGE_F;

#pragma unroll
        for (int ks = 0; ks < 2; ks++) {
            const int kb = ks * 32;
            uint32_t a[4][4], bhi[2][4], blo[2][4];
#pragma unroll
            for (int mt = 0; mt < 4; mt++) {
                uint32_t off = SWZ64((uint32_t)(
                    (wm * 64 + mt * 16 + (q & 1) * 8 + rin) * 64 + kb + (q >> 1) * 16));
                ldsm4(a[mt], stb + O_A + off);
            }
#pragma unroll
            for (int p = 0; p < 2; p++) {
                uint32_t off = SWZ64((uint32_t)(
                    (wn * 32 + p * 16 + (q >> 1) * 8 + rin) * 64 + kb + (q & 1) * 16));
                ldsm4(bhi[p], stb + O_BHI + off);
                ldsm4(blo[p], stb + O_BLO + off);
            }
#pragma unroll
            for (int mt = 0; mt < 4; mt++)
#pragma unroll
                for (int nt = 0; nt < 4; nt++) {
                    const uint32_t* bh = &bhi[nt >> 1][(nt & 1) * 2];
                    const uint32_t* bl = &blo[nt >> 1][(nt & 1) * 2];
                    mma_f16(acc[mt][nt], a[mt], bh);
                    mma_f16(acc[mt][nt], a[mt], bl);
                }
        }
    }

    const int r_base = row0 + wm * 64 + (lid >> 2);
    const int c_base = col0 + wn * 32 + (lid & 3) * 2;

    __nv_bfloat16* Dhi = (z == 0) ? qhi : (z == 1) ? khi : vhi;
    __nv_bfloat16* Dlo = (z == 0) ? qlo : (z == 1) ? klo : vlo;
    const int mode = (z == 2) ? 2 : 1;
    const float qs = (z == 0) ? QSCALE : 1.0f;
#pragma unroll
    for (int mt = 0; mt < 4; mt++)
#pragma unroll
        for (int nt = 0; nt < 4; nt++) {
            int gr = r_base + mt * 16;
            int gc = c_base + nt * 8;
            int hh = gc >> 6, d = gc & 63, ii = d >> 1;
            int b_ = gr >> 11;
            int s1 = gr & (SS - 1);
            int s2 = (gr + 8) & (SS - 1);
            float v0 = acc[mt][nt][0], v1 = acc[mt][nt][1];
            float v2 = acc[mt][nt][2], v3 = acc[mt][nt][3];
            if (mode == 1) {
                float2 cs1 = g_rope[(s1 << 5) + ii];
                float2 cs2 = g_rope[(s2 << 5) + ii];
                float t0 = v0 * cs1.x - v1 * cs1.y;
                v1 = (v0 * cs1.y + v1 * cs1.x) * qs; v0 = t0 * qs;
                t0 = v2 * cs2.x - v3 * cs2.y;
                v3 = (v2 * cs2.y + v3 * cs2.x) * qs; v2 = t0 * qs;
            }
            size_t o1 = ((size_t)((b_ * HH + hh) * SS + s1)) * 64 + d;
            size_t o2 = ((size_t)((b_ * HH + hh) * SS + s2)) * 64 + d;
            uint32_t h01 = cvt2_bf16(v0, v1);
            uint32_t h23 = cvt2_bf16(v2, v3);
            *reinterpret_cast<uint32_t*>(Dhi + o1) = h01;
            *reinterpret_cast<uint32_t*>(Dhi + o2) = h23;
            *reinterpret_cast<uint32_t*>(Dlo + o1) =
                cvt2_bf16(v0 - bf_lo_f(h01), v1 - bf_hi_f(h01));
            *reinterpret_cast<uint32_t*>(Dlo + o2) =
                cvt2_bf16(v2 - bf_lo_f(h23), v3 - bf_hi_f(h23));
        }
}

// ---------------------------------------------------------------------------
// Wo GEMM (bf16 3-term, round-13 proven): CTA 64x64, warp 32x32, BK=32,
// 3-stage. fp32 output. grid (16, 64).
// ---------------------------------------------------------------------------
#define BM2 64
#define BN2 64
#define A2_T (BM2 * BK * 2)              // 4096
#define B2_T (BN2 * BK * 2)              // 4096
#define STAGE2 (2 * A2_T + 2 * B2_T)     // 16384
#define GEMM64_SMEM (3 * STAGE2)         // 49152

__global__ void __launch_bounds__(128, 4) gemm_mma64(
    const __nv_bfloat16* __restrict__ Ahi, const __nv_bfloat16* __restrict__ Alo,
    const __nv_bfloat16* __restrict__ Bhi, const __nv_bfloat16* __restrict__ Blo,
    float* __restrict__ C) {
    extern __shared__ __align__(1024) char smem[];
    const uint32_t sb = smem_u32(smem);

    const int tid = threadIdx.x;
    const int wid = tid >> 5;
    const int lid = tid & 31;
    const int row0 = blockIdx.y * BM2;
    const int col0 = blockIdx.x * BN2;
    const int wm = wid & 1;
    const int wn = wid >> 1;              // 0..1

    const int O_AHI = 0, O_ALO = A2_T, O_BHI = 2 * A2_T, O_BLO = 2 * A2_T + B2_T;

    float acc[2][4][4] = {};

    auto load_tiles = [&](int st, int kt) {
        const uint32_t stb = sb + st * STAGE2;
        const int k0 = kt * BK;
#pragma unroll
        for (int i = 0; i < 2; i++) {
            int c = tid + i * 128;        // 0..255
            int r = c >> 2;               // 0..63
            int cb = (c & 3) * 16;
            uint32_t so = SWZ64((uint32_t)(r * 64 + cb));
            size_t ga = (size_t)(row0 + r) * EE + k0 + (c & 3) * 8;
            cp16(stb + O_AHI + so, Ahi + ga);
            cp16(stb + O_ALO + so, Alo + ga);
            size_t gb = (size_t)(col0 + r) * EE + k0 + (c & 3) * 8;
            cp16(stb + O_BHI + so, Bhi + gb);
            cp16(stb + O_BLO + so, Blo + gb);
        }
    };

    load_tiles(0, 0);
    CP_COMMIT();
    load_tiles(1, 1);
    CP_COMMIT();

    const int q = lid >> 3, rin = lid & 7;

    for (int kt = 0; kt < KTILES; kt++) {
        if (kt < KTILES - 1) { CP_WAIT(1); } else { CP_WAIT(0); }
        __syncthreads();
        if (kt + 2 < KTILES) {
            int st = kt + 2;
            st = st - (st / 3) * 3;
            load_tiles(st, kt + 2);
            CP_COMMIT();
        }

        const int cur = kt - (kt / 3) * 3;
        const uint32_t stb = sb + cur * STAGE2;

#pragma unroll
        for (int ks = 0; ks < 2; ks++) {
            const int kb = ks * 32;
            uint32_t ahi[2][4], alo[2][4], bhi[2][4], blo[2][4];
#pragma unroll
            for (int mt = 0; mt < 2; mt++) {
                uint32_t off = SWZ64((uint32_t)(
                    (wm * 32 + mt * 16 + (q & 1) * 8 + rin) * 64 + kb + (q >> 1) * 16));
                ldsm4(ahi[mt], stb + O_AHI + off);
                ldsm4(alo[mt], stb + O_ALO + off);
            }
#pragma unroll
            for (int p = 0; p < 2; p++) {
                uint32_t off = SWZ64((uint32_t)(
                    (wn * 32 + p * 16 + (q >> 1) * 8 + rin) * 64 + kb + (q & 1) * 16));
                ldsm4(bhi[p], stb + O_BHI + off);
                ldsm4(blo[p], stb + O_BLO + off);
            }
#pragma unroll
            for (int mt = 0; mt < 2; mt++)
#pragma unroll
                for (int nt = 0; nt < 4; nt++) {
                    const uint32_t* bh = &bhi[nt >> 1][(nt & 1) * 2];
                    const uint32_t* bl = &blo[nt >> 1][(nt & 1) * 2];
                    mma_bf16(acc[mt][nt], ahi[mt], bh);
                    mma_bf16(acc[mt][nt], ahi[mt], bl);
                    mma_bf16(acc[mt][nt], alo[mt], bh);
                }
        }
    }

    const int r_base = row0 + wm * 32 + (lid >> 2);
    const int c_base = col0 + wn * 32 + (lid & 3) * 2;
#pragma unroll
    for (int mt = 0; mt < 2; mt++)
#pragma unroll
        for (int nt = 0; nt < 4; nt++) {
            int r = r_base + mt * 16;
            int c = c_base + nt * 8;
            *reinterpret_cast<float2*>(C + (size_t)r * EE + c) =
                make_float2(acc[mt][nt][0], acc[mt][nt][1]);
            *reinterpret_cast<float2*>(C + (size_t)(r + 8) * EE + c) =
                make_float2(acc[mt][nt][2], acc[mt][nt][3]);
        }
}

// ---------------------------------------------------------------------------
// Warp-MMA causal flash attention (round-15 proven: Q in regs, 3-stage ring).
// ---------------------------------------------------------------------------
#define FQ 128
#define FK 64
#define KV_STAGE 32768
#define FLASH_SMEM (3 * KV_STAGE)   // 98304

__global__ void __launch_bounds__(128, 2) flash_mma(
    const __nv_bfloat16* __restrict__ qhi, const __nv_bfloat16* __restrict__ qlo,
    const __nv_bfloat16* __restrict__ khi, const __nv_bfloat16* __restrict__ klo,
    const __nv_bfloat16* __restrict__ vhi, const __nv_bfloat16* __restrict__ vlo,
    __nv_bfloat16* __restrict__ ohi, __nv_bfloat16* __restrict__ olo) {
    extern __shared__ __align__(1024) char smem[];
    const uint32_t sb = smem_u32(smem);
    const int tid = threadIdx.x;
    const int wid = tid >> 5;
    const int lid = tid & 31;
    const int bh = blockIdx.y;
    const int qt = gridDim.x - 1 - blockIdx.x;
    const int q0 = qt * FQ;
    const int b = bh >> 4, h = bh & 15;
    const int qq = lid >> 3, rin = lid & 7;

#pragma unroll
    for (int i = 0; i < 8; i++) {
        int c = i * 128 + tid;
        int r = c >> 3, cb = c & 7;
        uint32_t so = SWZ((uint32_t)(r * 128 + cb * 16));
        size_t g = ((size_t)bh * SS + q0 + r) * 64 + cb * 8;
        cp16(sb + so, qhi + g);
        cp16(sb + 16384 + so, qlo + g);
    }
    CP_COMMIT();
    CP_WAIT(0);
    __syncthreads();

    uint32_t qfh[2][4][4], qfl[2][4][4];
#pragma unroll
    for (int mt = 0; mt < 2; mt++)
#pragma unroll
        for (int kd = 0; kd < 4; kd++) {
            uint32_t off = SWZ((uint32_t)(
                (wid * 32 + mt * 16 + (qq & 1) * 8 + rin) * 128 +
                kd * 32 + (qq >> 1) * 16));
            ldsm4(qfh[mt][kd], sb + off);
            ldsm4(qfl[mt][kd], sb + 16384 + off);
        }
    __syncthreads();

    auto load_kv = [&](int st, int kt) {
        const uint32_t stb = sb + st * KV_STAGE;
        const size_t rb = (size_t)bh * SS + (size_t)kt * FK;
#pragma unroll
        for (int i = 0; i < 4; i++) {
            int c = i * 128 + tid;
            int r = c >> 3, cb = c & 7;
            uint32_t so = SWZ((uint32_t)(r * 128 + cb * 16));
            size_t g = (rb + r) * 64 + cb * 8;
            cp16(stb + so,         khi + g);
            cp16(stb + 8192 + so,  klo + g);
            cp16(stb + 16384 + so, vhi + g);
            cp16(stb + 24576 + so, vlo + g);
        }
    };

    float o[2][8][4] = {};
    float mrow[4] = {-1e30f, -1e30f, -1e30f, -1e30f};
    float lrow[4] = {};

    const int nkt = 2 * qt + 2;
    load_kv(0, 0);
    CP_COMMIT();
    load_kv(1, 1);
    CP_COMMIT();

    int cur = 0;

    for (int kt = 0; kt < nkt; kt++) {
        if (kt < nkt - 1) { CP_WAIT(1); } else { CP_WAIT(0); }
        __syncthreads();
        if (kt + 2 < nkt) {
            int st = cur + 2;
            if (st >= 3) st -= 3;
            load_kv(st, kt + 2);
            CP_COMMIT();
        }

        const uint32_t stb = sb + cur * KV_STAGE;
        cur++;
        if (cur == 3) cur = 0;
        const int k0 = kt * FK;

        float s[2][8][4] = {};
#pragma unroll
        for (int kd = 0; kd < 4; kd++) {
            uint32_t kh[4][4], kl[4][4];
#pragma unroll
            for (int p = 0; p < 4; p++) {
                uint32_t off = SWZ((uint32_t)(
                    (p * 16 + (qq >> 1) * 8 + rin) * 128 + kd * 32 + (qq & 1) * 16));
                ldsm4(kh[p], stb + off);
                ldsm4(kl[p], stb + 8192 + off);
            }
#pragma unroll
            for (int mt = 0; mt < 2; mt++)
#pragma unroll
                for (int nt = 0; nt < 8; nt++) {
                    const uint32_t* bhp = &kh[nt >> 1][(nt & 1) * 2];
                    const uint32_t* blp = &kl[nt >> 1][(nt & 1) * 2];
                    mma_bf16(s[mt][nt], qfh[mt][kd], bhp);
                    mma_bf16(s[mt][nt], qfh[mt][kd], blp);
                    mma_bf16(s[mt][nt], qfl[mt][kd], bhp);
                }
        }

        if ((k0 + FK - 1) > (q0 + wid * 32)) {
#pragma unroll
            for (int mt = 0; mt < 2; mt++)
#pragma unroll
                for (int nt = 0; nt < 8; nt++)
#pragma unroll
                    for (int c = 0; c < 4; c++) {
                        int row = q0 + wid * 32 + mt * 16 + (lid >> 2) + ((c >> 1) << 3);
                        int key = k0 + nt * 8 + 2 * (lid & 3) + (c & 1);
                        if (key > row) s[mt][nt][c] = -1e30f;
                    }
        }

#pragma unroll
        for (int mt = 0; mt < 2; mt++)
#pragma unroll
            for (int hf = 0; hf < 2; hf++) {
                const int ri = mt * 2 + hf;
                float mx = -1e30f;
#pragma unroll
                for (int nt = 0; nt < 8; nt++) {
                    mx = fmaxf(mx, s[mt][nt][hf * 2]);
                    mx = fmaxf(mx, s[mt][nt][hf * 2 + 1]);
                }
                mx = fmaxf(mx, __shfl_xor_sync(0xffffffff, mx, 1));
                mx = fmaxf(mx, __shfl_xor_sync(0xffffffff, mx, 2));
                float mnew = fmaxf(mrow[ri], mx);
                float corr = fast_exp2(mrow[ri] - mnew);
                mrow[ri] = mnew;
                float lsum = 0.0f;
#pragma unroll
                for (int nt = 0; nt < 8; nt++) {
                    float p0 = fast_exp2(s[mt][nt][hf * 2] - mnew);
                    float p1 = fast_exp2(s[mt][nt][hf * 2 + 1] - mnew);
                    s[mt][nt][hf * 2] = p0;
                    s[mt][nt][hf * 2 + 1] = p1;
                    lsum += p0 + p1;
                }
                lrow[ri] = lrow[ri] * corr + lsum;
#pragma unroll
                for (int dt = 0; dt < 8; dt++) {
                    o[mt][dt][hf * 2] *= corr;
                    o[mt][dt][hf * 2 + 1] *= corr;
                }
            }

#pragma unroll
        for (int kk = 0; kk < 4; kk++) {
            uint32_t ph[2][4], pl[2][4];
#pragma unroll
            for (int mt = 0; mt < 2; mt++) {
#pragma unroll
                for (int half = 0; half < 2; half++) {
                    float p0 = s[mt][2 * kk + half][0], p1 = s[mt][2 * kk + half][1];
                    float p2 = s[mt][2 * kk + half][2], p3 = s[mt][2 * kk + half][3];
                    uint32_t h01 = cvt2_bf16(p0, p1);
                    uint32_t h23 = cvt2_bf16(p2, p3);
                    ph[mt][half * 2 + 0] = h01;
                    ph[mt][half * 2 + 1] = h23;
                    pl[mt][half * 2 + 0] =
                        cvt2_bf16(p0 - bf_lo_f(h01), p1 - bf_hi_f(h01));
                    pl[mt][half * 2 + 1] =
                        cvt2_bf16(p2 - bf_lo_f(h23), p3 - bf_hi_f(h23));
                }
            }
            uint32_t vh[4][4], vl[4][4];
#pragma unroll
            for (int dp = 0; dp < 4; dp++) {
                uint32_t off = SWZ((uint32_t)(
                    (kk * 16 + (qq & 1) * 8 + rin) * 128 + dp * 32 + (qq >> 1) * 16));
                ldsm4t(vh[dp], stb + 16384 + off);
                ldsm4t(vl[dp], stb + 24576 + off);
            }
#pragma unroll
            for (int mt = 0; mt < 2; mt++)
#pragma unroll
                for (int dt = 0; dt < 8; dt++) {
                    const uint32_t* bhp = &vh[dt >> 1][(dt & 1) * 2];
                    const uint32_t* blp = &vl[dt >> 1][(dt & 1) * 2];
                    mma_bf16(o[mt][dt], ph[mt], bhp);
                    mma_bf16(o[mt][dt], ph[mt], blp);
                    mma_bf16(o[mt][dt], pl[mt], bhp);
                }
        }
    }

    float inv[4];
#pragma unroll
    for (int ri = 0; ri < 4; ri++) {
        float l = lrow[ri];
        l += __shfl_xor_sync(0xffffffff, l, 1);
        l += __shfl_xor_sync(0xffffffff, l, 2);
        inv[ri] = 1.0f / l;
    }

#pragma unroll
    for (int mt = 0; mt < 2; mt++)
#pragma unroll
        for (int dt = 0; dt < 8; dt++) {
            int col = h * 64 + dt * 8 + 2 * (lid & 3);
#pragma unroll
            for (int hf = 0; hf < 2; hf++) {
                int row = q0 + wid * 32 + mt * 16 + (lid >> 2) + hf * 8;
                float v0 = o[mt][dt][hf * 2] * inv[mt * 2 + hf];
                float v1 = o[mt][dt][hf * 2 + 1] * inv[mt * 2 + hf];
                size_t idx = ((size_t)(b * SS + row)) * EE + col;
                uint32_t h01 = cvt2_bf16(v0, v1);
                *reinterpret_cast<uint32_t*>(ohi + idx) = h01;
                *reinterpret_cast<uint32_t*>(olo + idx) =
                    cvt2_bf16(v0 - bf_lo_f(h01), v1 - bf_hi_f(h01));
            }
        }
}

// ---------------------------------------------------------------------------
// Launch
// ---------------------------------------------------------------------------
extern "C" void kernel_launch(void* const* d_in, const int* in_sizes, int n_in,
                              void* d_out, int out_size) {
    const float* x  = (const float*)d_in[0];
    const float* Wq = (const float*)d_in[1];
    const float* Wk = (const float*)d_in[2];
    const float* Wv = (const float*)d_in[3];
    const float* Wo = (const float*)d_in[4];
    float* out = (float*)d_out;

    __half *xh, *wfh, *wfl;
    __nv_bfloat16 *whi, *wlo, *ahi, *alo, *qhi, *qlo, *khi, *klo, *vhi, *vlo;
    cudaGetSymbolAddress((void**)&xh, g_xh);
    cudaGetSymbolAddress((void**)&wfh, g_wfh);
    cudaGetSymbolAddress((void**)&wfl, g_wfl);
    cudaGetSymbolAddress((void**)&whi, g_whi);
    cudaGetSymbolAddress((void**)&wlo, g_wlo);
    cudaGetSymbolAddress((void**)&ahi, g_ahi);
    cudaGetSymbolAddress((void**)&alo, g_alo);
    cudaGetSymbolAddress((void**)&qhi, g_qhi);
    cudaGetSymbolAddress((void**)&qlo, g_qlo);
    cudaGetSymbolAddress((void**)&khi, g_khi);
    cudaGetSymbolAddress((void**)&klo, g_klo);
    cudaGetSymbolAddress((void**)&vhi, g_vhi);
    cudaGetSymbolAddress((void**)&vlo, g_vlo);

    cudaFuncSetAttribute(gemm_qkv, cudaFuncAttributeMaxDynamicSharedMemorySize,
                         GEMM_SMEM);
    cudaFuncSetAttribute(gemm_mma64, cudaFuncAttributeMaxDynamicSharedMemorySize,
                         GEMM64_SMEM);
    cudaFuncSetAttribute(flash_mma, cudaFuncAttributeMaxDynamicSharedMemorySize,
                         FLASH_SMEM);

    // Fused prelude
    prelude_kernel<<<(PRELUDE_N + 255) / 256, 256>>>(x, Wq, Wk, Wv, Wo,
                                                     xh, wfh, wfl, whi, wlo);

    // fp16 2-term fused QKV GEMMs
    dim3 gq(EE / BN, MROWS / BM, 3);   // (16, 32, 3)
    gemm_qkv<<<gq, 128, GEMM_SMEM>>>(xh, wfh, wfl,
                                     qhi, qlo, khi, klo, vhi, vlo);

    dim3 fg(SS / FQ, BB * HH);         // (16, 32)
    flash_mma<<<fg, 128, FLASH_SMEM>>>(qhi, qlo, khi, klo, vhi, vlo, ahi, alo);

    // Output projection (bf16 3-term)
    dim3 go(EE / BN2, MROWS / BM2);    // (16, 64)
    gemm_mma64<<<go, 128, GEMM64_SMEM>>>(ahi, alo, whi, wlo, out);
}